// round 6
// baseline (speedup 1.0000x reference)
#include <cuda_runtime.h>
#include <cuda_bf16.h>
#include <math.h>

#define BATCH 32
#define HDIM 112
#define WDIM 112
#define CDIM 192
#define HW (HDIM*WDIM)          // 12544
#define C4 (CDIM/4)             // 48

// ---------------- scratch (device globals; no allocation) ----------------
__device__ float  g_part_sum[BATCH*HDIM*CDIM];  // per-(b,row) channel sums
__device__ float  g_part_max[BATCH*HDIM*CDIM];  // per-(b,row) channel maxes
__device__ float  g_scale[BATCH*CDIM];          // fused se*channel_att per (b,c)
__device__ float2 g_sp[BATCH*HW];               // per-pixel {avg_c, max_c}

// monotone float -> unsigned mapping for smem atomicMax
__device__ __forceinline__ unsigned f2u_ord(float f) {
    unsigned u = __float_as_uint(f);
    return (u & 0x80000000u) ? ~u : (u | 0x80000000u);
}
__device__ __forceinline__ float u2f_ord(unsigned u) {
    return (u & 0x80000000u) ? __uint_as_float(u & 0x7fffffffu) : __uint_as_float(~u);
}
__device__ __forceinline__ float sigm(float v) { return 1.0f / (1.0f + expf(-v)); }
__device__ __forceinline__ float swishf(float v) { return v * sigm(v); }

// ---------------- kernel 1: fused pools (one pass over x) ----------------
// grid (H, B), block 256 (8 warps). Each block = one image row (112 pixels).
// Warp-per-pixel loads are coalesced float2. Per-pixel channel reductions go
// through a transposed smem array (stride 33, conflict-free) instead of a
// shuffle butterfly. Channel partials are written per-(b,row) -- no atomics
// to global, no init kernel.
__global__ void k_pool(const float* __restrict__ x) {
    int b = blockIdx.y, h = blockIdx.x;
    int warp = threadIdx.x >> 5, lane = threadIdx.x & 31;
    int tid = threadIdx.x;

    __shared__ float    s_ps[WDIM*33];      // per-pixel per-lane sum partials
    __shared__ float    s_pm[WDIM*33];      // per-pixel per-lane max partials
    __shared__ float    s_sum[CDIM];        // per-channel block sums
    __shared__ unsigned s_max[CDIM];        // per-channel block maxes (ordered)

    if (tid < CDIM) { s_sum[tid] = 0.0f; s_max[tid] = 0u; }
    __syncthreads();

    float csum[6] = {0.f,0.f,0.f,0.f,0.f,0.f};
    float cmax[6] = {-3.4e38f,-3.4e38f,-3.4e38f,-3.4e38f,-3.4e38f,-3.4e38f};

    const float* xrow = x + (size_t)(b*HW + h*WDIM) * CDIM;

    for (int p = warp; p < WDIM; p += 8) {
        const float2* px = (const float2*)(xrow + p*CDIM);
        float2 v0 = px[lane];
        float2 v1 = px[lane+32];
        float2 v2 = px[lane+64];

        csum[0] += v0.x; csum[1] += v0.y;
        csum[2] += v1.x; csum[3] += v1.y;
        csum[4] += v2.x; csum[5] += v2.y;
        cmax[0] = fmaxf(cmax[0], v0.x); cmax[1] = fmaxf(cmax[1], v0.y);
        cmax[2] = fmaxf(cmax[2], v1.x); cmax[3] = fmaxf(cmax[3], v1.y);
        cmax[4] = fmaxf(cmax[4], v2.x); cmax[5] = fmaxf(cmax[5], v2.y);

        float psum = (v0.x + v0.y) + (v1.x + v1.y) + (v2.x + v2.y);
        float pmax = fmaxf(fmaxf(fmaxf(v0.x, v0.y), fmaxf(v1.x, v1.y)),
                           fmaxf(v2.x, v2.y));
        s_ps[p*33 + lane] = psum;
        s_pm[p*33 + lane] = pmax;
    }

    // block-level channel combine (smem atomics; 8-way conflict per address)
    #pragma unroll
    for (int j = 0; j < 3; j++) {
        int c = 2*(lane + 32*j);
        atomicAdd(&s_sum[c],   csum[2*j]);
        atomicAdd(&s_sum[c+1], csum[2*j+1]);
        atomicMax(&s_max[c],   f2u_ord(cmax[2*j]));
        atomicMax(&s_max[c+1], f2u_ord(cmax[2*j+1]));
    }
    __syncthreads();

    // phase 2: per-pixel totals (thread t reduces 32 lane-partials of pixel t)
    if (tid < WDIM) {
        float s = 0.0f, m = -3.4e38f;
        #pragma unroll 8
        for (int j = 0; j < 32; j++) {
            s += s_ps[tid*33 + j];
            m = fmaxf(m, s_pm[tid*33 + j]);
        }
        g_sp[b*HW + h*WDIM + tid] = make_float2(s * (1.0f/192.0f), m);
    }
    // phase 3: per-row channel partials to global (no atomics)
    if (tid < CDIM) {
        g_part_sum[(b*HDIM + h)*CDIM + tid] = s_sum[tid];
        g_part_max[(b*HDIM + h)*CDIM + tid] = u2f_ord(s_max[tid]);
    }
}

// ---------------- kernel 2: reduce partials + SE/CBAM MLPs ----------------
// grid B, block 192
__global__ void k_mlp(const float* __restrict__ se_w1, const float* __restrict__ se_b1,
                      const float* __restrict__ se_w2, const float* __restrict__ se_b2,
                      const float* __restrict__ mlp_w1, const float* __restrict__ mlp_b1,
                      const float* __restrict__ mlp_w2, const float* __restrict__ mlp_b2) {
    int b = blockIdx.x, t = threadIdx.x;
    __shared__ float avg[CDIM], mx[CDIM], hse[12], ha[24], hm[24];

    {
        const float* ps = g_part_sum + (size_t)b*HDIM*CDIM + t;
        const float* pm = g_part_max + (size_t)b*HDIM*CDIM + t;
        float s = 0.0f, m = -3.4e38f;
        #pragma unroll 4
        for (int h2 = 0; h2 < HDIM; h2++) {
            s += ps[h2*CDIM];
            m = fmaxf(m, pm[h2*CDIM]);
        }
        avg[t] = s * (1.0f/(float)HW);
        mx[t]  = m;
    }
    __syncthreads();

    if (t < 12) {                          // SE hidden (192 -> 12), swish
        float a = se_b1[t];
        for (int c = 0; c < CDIM; c++) a += avg[c] * se_w1[c*12 + t];
        hse[t] = swishf(a);
    } else if (t >= 32 && t < 56) {        // CBAM hidden (192 -> 24), avg & max
        int j = t - 32;
        float a = mlp_b1[j], m = mlp_b1[j];
        for (int c = 0; c < CDIM; c++) {
            float w = mlp_w1[c*24 + j];
            a += avg[c]*w; m += mx[c]*w;
        }
        ha[j] = swishf(a); hm[j] = swishf(m);
    }
    __syncthreads();

    float s = se_b2[t];
    #pragma unroll
    for (int j = 0; j < 12; j++) s += hse[j] * se_w2[j*CDIM + t];
    float catt = 2.0f * mlp_b2[t];
    #pragma unroll
    for (int j = 0; j < 24; j++) catt += (ha[j] + hm[j]) * mlp_w2[j*CDIM + t];

    g_scale[b*CDIM + t] = sigm(s) * sigm(catt);
}

// ---------------- kernel 3: fused 7x7 conv + sigmoid + elementwise apply ----
// grid (H, B), block (48, 8) = 384 threads. Per block: build 7x118 float2 tile
// of g_sp (L2-hot), 112 threads compute spatial attention for the row into
// smem, then all threads stream x -> out with float4.
__global__ void k_apply(const float* __restrict__ x, float* __restrict__ out,
                        const float* __restrict__ conv_k, const float* __restrict__ conv_b) {
    int b = blockIdx.y, h = blockIdx.x;
    int tid = threadIdx.y * C4 + threadIdx.x;

    __shared__ float2 tile[7][WDIM+6];     // rows h-3..h+3, cols -3..114
    __shared__ float  sa[WDIM];
    __shared__ float2 kk2[49];
    __shared__ float  kb;

    for (int i = tid; i < 7*(WDIM+6); i += 384) {
        int kh = i / (WDIM+6);
        int ww = i - kh*(WDIM+6);
        int gh = h + kh - 3, gw = ww - 3;
        float2 v = make_float2(0.0f, 0.0f);
        if (gh >= 0 && gh < HDIM && gw >= 0 && gw < WDIM)
            v = g_sp[b*HW + gh*WDIM + gw];
        tile[kh][ww] = v;
    }
    if (tid < 49) kk2[tid] = ((const float2*)conv_k)[tid];
    if (tid == 0) kb = conv_b[0];
    __syncthreads();

    if (tid < WDIM) {
        float acc = kb;
        #pragma unroll
        for (int kh = 0; kh < 7; kh++)
            #pragma unroll
            for (int kw = 0; kw < 7; kw++) {
                float2 v = tile[kh][tid+kw];
                float2 k = kk2[kh*7+kw];
                acc += v.x * k.x + v.y * k.y;
            }
        sa[tid] = sigm(acc);
    }
    __syncthreads();

    int c4 = threadIdx.x, ty = threadIdx.y;
    float4 sc = ((const float4*)(g_scale + b*CDIM))[c4];
    const float4* xp = (const float4*)x + (size_t)(b*HW + h*WDIM) * C4;
    float4*       op = (float4*)out     + (size_t)(b*HW + h*WDIM) * C4;

    #pragma unroll 7
    for (int p = ty; p < WDIM; p += 8) {
        float s = sa[p];
        float4 v = xp[p*C4 + c4];
        v.x *= sc.x * s; v.y *= sc.y * s;
        v.z *= sc.z * s; v.w *= sc.w * s;
        op[p*C4 + c4] = v;
    }
}

// ---------------- launch ----------------
extern "C" void kernel_launch(void* const* d_in, const int* in_sizes, int n_in,
                              void* d_out, int out_size) {
    const float* x      = (const float*)d_in[0];
    const float* se_w1  = (const float*)d_in[1];
    const float* se_b1  = (const float*)d_in[2];
    const float* se_w2  = (const float*)d_in[3];
    const float* se_b2  = (const float*)d_in[4];
    const float* mlp_w1 = (const float*)d_in[5];
    const float* mlp_b1 = (const float*)d_in[6];
    const float* mlp_w2 = (const float*)d_in[7];
    const float* mlp_b2 = (const float*)d_in[8];
    const float* conv_k = (const float*)d_in[9];
    const float* conv_b = (const float*)d_in[10];
    float* out = (float*)d_out;

    k_pool<<<dim3(HDIM, BATCH), 256>>>(x);
    k_mlp<<<BATCH, CDIM>>>(se_w1, se_b1, se_w2, se_b2, mlp_w1, mlp_b1, mlp_w2, mlp_b2);
    k_apply<<<dim3(HDIM, BATCH), dim3(C4, 8)>>>(x, out, conv_k, conv_b);
}

// round 7
// speedup vs baseline: 1.1348x; 1.1348x over previous
#include <cuda_runtime.h>
#include <cuda_bf16.h>
#include <math.h>

#define BATCH 32
#define HDIM 112
#define WDIM 112
#define CDIM 192
#define HW (HDIM*WDIM)          // 12544
#define C4 (CDIM/4)             // 48

// ---------------- scratch (device globals; no allocation) ----------------
__device__ float    g_sum[BATCH*CDIM];          // spatial sum per (b,c)
__device__ unsigned g_maxu[BATCH*CDIM];         // spatial max per (b,c), ordered-uint
__device__ float    g_scale[BATCH*CDIM];        // fused se*channel_att per (b,c)
__device__ float2   g_sp[BATCH*HW];             // per-pixel {avg_c, max_c}

// monotone float -> unsigned mapping for atomicMax
__device__ __forceinline__ unsigned f2u_ord(float f) {
    unsigned u = __float_as_uint(f);
    return (u & 0x80000000u) ? ~u : (u | 0x80000000u);
}
__device__ __forceinline__ float u2f_ord(unsigned u) {
    return (u & 0x80000000u) ? __uint_as_float(u & 0x7fffffffu) : __uint_as_float(~u);
}
__device__ __forceinline__ float sigm(float v) { return 1.0f / (1.0f + expf(-v)); }
__device__ __forceinline__ float swishf(float v) { return v * sigm(v); }

// ---------------- kernel 0: init accumulators ----------------
__global__ void k_init() {
    int i = blockIdx.x * 256 + threadIdx.x;
    if (i < BATCH*CDIM) { g_sum[i] = 0.0f; g_maxu[i] = 0u; }
}

// ---------------- kernel 1: fused pools (one pass over x) ----------------
// grid (H, B), block 256 (8 warps). Each block = one image row (112 pixels).
// Each warp processes PIXEL PAIRS (p, p+8) per iteration: 6 independent
// coalesced float2 loads in flight (doubled MLP vs single-pixel version,
// which measured DRAM=55.8% / issue=22.9% -- latency bound).
__global__ void k_pool(const float* __restrict__ x) {
    int b = blockIdx.y, h = blockIdx.x;
    int warp = threadIdx.x >> 5, lane = threadIdx.x & 31;

    __shared__ float    s_sum[CDIM];
    __shared__ unsigned s_max[CDIM];
    if (threadIdx.x < CDIM) { s_sum[threadIdx.x] = 0.0f; s_max[threadIdx.x] = 0u; }
    __syncthreads();

    float csum[6] = {0.f,0.f,0.f,0.f,0.f,0.f};
    float cmax[6] = {-3.4e38f,-3.4e38f,-3.4e38f,-3.4e38f,-3.4e38f,-3.4e38f};

    const float* xrow = x + (size_t)(b*HW + h*WDIM) * CDIM;
    float2* sprow = g_sp + b*HW + h*WDIM;

    // 7 iterations per warp; pairs (warp + 16*i, warp + 16*i + 8)
    #pragma unroll 2
    for (int p = warp; p < WDIM; p += 16) {
        const float2* pxA = (const float2*)(xrow + p*CDIM);
        const float2* pxB = (const float2*)(xrow + (p+8)*CDIM);
        float2 a0 = pxA[lane], a1 = pxA[lane+32], a2 = pxA[lane+64];
        float2 b0 = pxB[lane], b1 = pxB[lane+32], b2 = pxB[lane+64];

        csum[0] += a0.x + b0.x;  csum[1] += a0.y + b0.y;
        csum[2] += a1.x + b1.x;  csum[3] += a1.y + b1.y;
        csum[4] += a2.x + b2.x;  csum[5] += a2.y + b2.y;
        cmax[0] = fmaxf(cmax[0], fmaxf(a0.x, b0.x));
        cmax[1] = fmaxf(cmax[1], fmaxf(a0.y, b0.y));
        cmax[2] = fmaxf(cmax[2], fmaxf(a1.x, b1.x));
        cmax[3] = fmaxf(cmax[3], fmaxf(a1.y, b1.y));
        cmax[4] = fmaxf(cmax[4], fmaxf(a2.x, b2.x));
        cmax[5] = fmaxf(cmax[5], fmaxf(a2.y, b2.y));

        float psA = (a0.x + a0.y) + (a1.x + a1.y) + (a2.x + a2.y);
        float psB = (b0.x + b0.y) + (b1.x + b1.y) + (b2.x + b2.y);
        float pmA = fmaxf(fmaxf(fmaxf(a0.x,a0.y), fmaxf(a1.x,a1.y)), fmaxf(a2.x,a2.y));
        float pmB = fmaxf(fmaxf(fmaxf(b0.x,b0.y), fmaxf(b1.x,b1.y)), fmaxf(b2.x,b2.y));

        #pragma unroll
        for (int o = 16; o > 0; o >>= 1) {
            psA += __shfl_xor_sync(0xffffffffu, psA, o);
            psB += __shfl_xor_sync(0xffffffffu, psB, o);
            pmA = fmaxf(pmA, __shfl_xor_sync(0xffffffffu, pmA, o));
            pmB = fmaxf(pmB, __shfl_xor_sync(0xffffffffu, pmB, o));
        }
        if (lane == 0) {
            sprow[p]   = make_float2(psA * (1.0f/192.0f), pmA);
            sprow[p+8] = make_float2(psB * (1.0f/192.0f), pmB);
        }
    }

    // block-level channel combine (smem atomics)
    #pragma unroll
    for (int j = 0; j < 3; j++) {
        int c = 2*(lane + 32*j);
        atomicAdd(&s_sum[c],   csum[2*j]);
        atomicAdd(&s_sum[c+1], csum[2*j+1]);
        atomicMax(&s_max[c],   f2u_ord(cmax[2*j]));
        atomicMax(&s_max[c+1], f2u_ord(cmax[2*j+1]));
    }
    __syncthreads();
    // one global atomic per channel per block (112 blocks collide per addr)
    if (threadIdx.x < CDIM) {
        atomicAdd(&g_sum[b*CDIM + threadIdx.x], s_sum[threadIdx.x]);
        atomicMax(&g_maxu[b*CDIM + threadIdx.x], s_max[threadIdx.x]);
    }
}

// ---------------- kernel 2: SE + CBAM-channel MLPs, fused scale ----------------
// grid B, block 192
__global__ void k_mlp(const float* __restrict__ se_w1, const float* __restrict__ se_b1,
                      const float* __restrict__ se_w2, const float* __restrict__ se_b2,
                      const float* __restrict__ mlp_w1, const float* __restrict__ mlp_b1,
                      const float* __restrict__ mlp_w2, const float* __restrict__ mlp_b2) {
    int b = blockIdx.x, t = threadIdx.x;
    __shared__ float avg[CDIM], mx[CDIM], hse[12], ha[24], hm[24];

    avg[t] = g_sum[b*CDIM + t] * (1.0f/(float)HW);
    mx[t]  = u2f_ord(g_maxu[b*CDIM + t]);
    __syncthreads();

    if (t < 12) {                          // SE hidden (192 -> 12), swish
        float a = se_b1[t];
        for (int c = 0; c < CDIM; c++) a += avg[c] * se_w1[c*12 + t];
        hse[t] = swishf(a);
    } else if (t >= 32 && t < 56) {        // CBAM hidden (192 -> 24), avg & max
        int j = t - 32;
        float a = mlp_b1[j], m = mlp_b1[j];
        for (int c = 0; c < CDIM; c++) {
            float w = mlp_w1[c*24 + j];
            a += avg[c]*w; m += mx[c]*w;
        }
        ha[j] = swishf(a); hm[j] = swishf(m);
    }
    __syncthreads();

    float s = se_b2[t];
    #pragma unroll
    for (int j = 0; j < 12; j++) s += hse[j] * se_w2[j*CDIM + t];
    float catt = 2.0f * mlp_b2[t];
    #pragma unroll
    for (int j = 0; j < 24; j++) catt += (ha[j] + hm[j]) * mlp_w2[j*CDIM + t];

    g_scale[b*CDIM + t] = sigm(s) * sigm(catt);
}

// ---------------- kernel 3: fused 7x7 conv + sigmoid + elementwise apply ----
// grid (H, B), block (48, 8) = 384 threads. Per block: build 7x118 float2 tile
// of g_sp (L2-hot), 112 threads compute spatial attention for the row into
// smem, then all threads stream x -> out with float4.
__global__ void k_apply(const float* __restrict__ x, float* __restrict__ out,
                        const float* __restrict__ conv_k, const float* __restrict__ conv_b) {
    int b = blockIdx.y, h = blockIdx.x;
    int tid = threadIdx.y * C4 + threadIdx.x;

    __shared__ float2 tile[7][WDIM+6];     // rows h-3..h+3, cols -3..114
    __shared__ float  sa[WDIM];
    __shared__ float2 kk2[49];
    __shared__ float  kb;

    for (int i = tid; i < 7*(WDIM+6); i += 384) {
        int kh = i / (WDIM+6);
        int ww = i - kh*(WDIM+6);
        int gh = h + kh - 3, gw = ww - 3;
        float2 v = make_float2(0.0f, 0.0f);
        if (gh >= 0 && gh < HDIM && gw >= 0 && gw < WDIM)
            v = g_sp[b*HW + gh*WDIM + gw];
        tile[kh][ww] = v;
    }
    if (tid < 49) kk2[tid] = ((const float2*)conv_k)[tid];
    if (tid == 0) kb = conv_b[0];
    __syncthreads();

    if (tid < WDIM) {
        float acc = kb;
        #pragma unroll
        for (int kh = 0; kh < 7; kh++)
            #pragma unroll
            for (int kw = 0; kw < 7; kw++) {
                float2 v = tile[kh][tid+kw];
                float2 k = kk2[kh*7+kw];
                acc += v.x * k.x + v.y * k.y;
            }
        sa[tid] = sigm(acc);
    }
    __syncthreads();

    int c4 = threadIdx.x, ty = threadIdx.y;
    float4 sc = ((const float4*)(g_scale + b*CDIM))[c4];
    const float4* xp = (const float4*)x + (size_t)(b*HW + h*WDIM) * C4;
    float4*       op = (float4*)out     + (size_t)(b*HW + h*WDIM) * C4;

    #pragma unroll 7
    for (int p = ty; p < WDIM; p += 8) {
        float s = sa[p];
        float4 v = xp[p*C4 + c4];
        v.x *= sc.x * s; v.y *= sc.y * s;
        v.z *= sc.z * s; v.w *= sc.w * s;
        op[p*C4 + c4] = v;
    }
}

// ---------------- launch ----------------
extern "C" void kernel_launch(void* const* d_in, const int* in_sizes, int n_in,
                              void* d_out, int out_size) {
    const float* x      = (const float*)d_in[0];
    const float* se_w1  = (const float*)d_in[1];
    const float* se_b1  = (const float*)d_in[2];
    const float* se_w2  = (const float*)d_in[3];
    const float* se_b2  = (const float*)d_in[4];
    const float* mlp_w1 = (const float*)d_in[5];
    const float* mlp_b1 = (const float*)d_in[6];
    const float* mlp_w2 = (const float*)d_in[7];
    const float* mlp_b2 = (const float*)d_in[8];
    const float* conv_k = (const float*)d_in[9];
    const float* conv_b = (const float*)d_in[10];
    float* out = (float*)d_out;

    k_init<<<(BATCH*CDIM + 255)/256, 256>>>();
    k_pool<<<dim3(HDIM, BATCH), 256>>>(x);
    k_mlp<<<BATCH, CDIM>>>(se_w1, se_b1, se_w2, se_b2, mlp_w1, mlp_b1, mlp_w2, mlp_b2);
    k_apply<<<dim3(HDIM, BATCH), dim3(C4, 8)>>>(x, out, conv_k, conv_b);
}

// round 8
// speedup vs baseline: 1.1489x; 1.0124x over previous
#include <cuda_runtime.h>
#include <cuda_bf16.h>
#include <math.h>

#define BATCH 32
#define HDIM 112
#define WDIM 112
#define CDIM 192
#define HW (HDIM*WDIM)          // 12544
#define C4 (CDIM/4)             // 48

// ---------------- scratch (device globals; no allocation) ----------------
__device__ float    g_sum[BATCH*CDIM];          // spatial sum per (b,c)
__device__ unsigned g_maxu[BATCH*CDIM];         // spatial max per (b,c), ordered-uint
__device__ float    g_scale[BATCH*CDIM];        // fused se*channel_att per (b,c)
__device__ float2   g_sp[BATCH*HW];             // per-pixel {avg_c, max_c}
__device__ float    g_sa[BATCH*HW];             // spatial attention per pixel

__device__ __forceinline__ unsigned f2u_ord(float f) {
    unsigned u = __float_as_uint(f);
    return (u & 0x80000000u) ? ~u : (u | 0x80000000u);
}
__device__ __forceinline__ float u2f_ord(unsigned u) {
    return (u & 0x80000000u) ? __uint_as_float(u & 0x7fffffffu) : __uint_as_float(~u);
}
__device__ __forceinline__ float sigm(float v) { return 1.0f / (1.0f + expf(-v)); }
__device__ __forceinline__ float swishf(float v) { return v * sigm(v); }

// ---------------- kernel 0: init accumulators ----------------
__global__ void k_init() {
    int i = blockIdx.x * 256 + threadIdx.x;
    if (i < BATCH*CDIM) { g_sum[i] = 0.0f; g_maxu[i] = 0u; }
}

// ---------------- kernel 1: fused pools (one pass over x) ----------------
// grid (56, B), block 256 (8 warps). Each block = TWO image rows (224 px).
// Each warp handles 28 pixels as 7 groups of 4, with software prefetch:
// group i+1's 12 float2 loads are issued before group i's reduction, so the
// DRAM latency overlaps the butterfly instead of alternating with it
// (R7 measured issue=22.9%, DRAM=55.8% -- serial load/compute phases).
__global__ void __launch_bounds__(256, 4) k_pool(const float* __restrict__ x) {
    int b = blockIdx.y;
    int h0 = blockIdx.x * 2;
    int warp = threadIdx.x >> 5, lane = threadIdx.x & 31;

    __shared__ float    s_sum[CDIM];
    __shared__ unsigned s_max[CDIM];
    if (threadIdx.x < CDIM) { s_sum[threadIdx.x] = 0.0f; s_max[threadIdx.x] = 0u; }
    __syncthreads();

    float csum[6] = {0.f,0.f,0.f,0.f,0.f,0.f};
    float cmax[6] = {-3.4e38f,-3.4e38f,-3.4e38f,-3.4e38f,-3.4e38f,-3.4e38f};

    const float* xbase = x + (size_t)(b*HW + h0*WDIM) * CDIM;   // 224 pixels
    float2* spbase = g_sp + b*HW + h0*WDIM;

    float2 cur[12];
    int p = warp * 4;
    #pragma unroll
    for (int q = 0; q < 4; q++)
        #pragma unroll
        for (int j = 0; j < 3; j++)
            cur[q*3+j] = __ldcs((const float2*)(xbase + (size_t)(p+q)*CDIM) + lane + 32*j);

    #pragma unroll
    for (int it = 0; it < 7; it++) {
        float2 nxt[12];
        int pn = p + 32;
        if (it < 6) {
            #pragma unroll
            for (int q = 0; q < 4; q++)
                #pragma unroll
                for (int j = 0; j < 3; j++)
                    nxt[q*3+j] = __ldcs((const float2*)(xbase + (size_t)(pn+q)*CDIM) + lane + 32*j);
        }

        float ps[4], pm[4];
        #pragma unroll
        for (int q = 0; q < 4; q++) {
            float2 v0 = cur[q*3], v1 = cur[q*3+1], v2 = cur[q*3+2];
            csum[0] += v0.x; csum[1] += v0.y;
            csum[2] += v1.x; csum[3] += v1.y;
            csum[4] += v2.x; csum[5] += v2.y;
            cmax[0] = fmaxf(cmax[0], v0.x); cmax[1] = fmaxf(cmax[1], v0.y);
            cmax[2] = fmaxf(cmax[2], v1.x); cmax[3] = fmaxf(cmax[3], v1.y);
            cmax[4] = fmaxf(cmax[4], v2.x); cmax[5] = fmaxf(cmax[5], v2.y);
            ps[q] = (v0.x + v0.y) + (v1.x + v1.y) + (v2.x + v2.y);
            pm[q] = fmaxf(fmaxf(fmaxf(v0.x,v0.y), fmaxf(v1.x,v1.y)), fmaxf(v2.x,v2.y));
        }
        #pragma unroll
        for (int o = 16; o > 0; o >>= 1) {
            #pragma unroll
            for (int q = 0; q < 4; q++) {
                ps[q] += __shfl_xor_sync(0xffffffffu, ps[q], o);
                pm[q] = fmaxf(pm[q], __shfl_xor_sync(0xffffffffu, pm[q], o));
            }
        }
        if (lane < 4) spbase[p + lane] = make_float2(ps[lane] * (1.0f/192.0f), pm[lane]);

        #pragma unroll
        for (int k = 0; k < 12; k++) cur[k] = nxt[k];
        p = pn;
    }

    #pragma unroll
    for (int j = 0; j < 3; j++) {
        int c = 2*(lane + 32*j);
        atomicAdd(&s_sum[c],   csum[2*j]);
        atomicAdd(&s_sum[c+1], csum[2*j+1]);
        atomicMax(&s_max[c],   f2u_ord(cmax[2*j]));
        atomicMax(&s_max[c+1], f2u_ord(cmax[2*j+1]));
    }
    __syncthreads();
    if (threadIdx.x < CDIM) {
        atomicAdd(&g_sum[b*CDIM + threadIdx.x], s_sum[threadIdx.x]);
        atomicMax(&g_maxu[b*CDIM + threadIdx.x], s_max[threadIdx.x]);
    }
}

// ---------------- kernel 2: SE + CBAM-channel MLPs, fused scale ----------------
// grid B, block 192
__global__ void k_mlp(const float* __restrict__ se_w1, const float* __restrict__ se_b1,
                      const float* __restrict__ se_w2, const float* __restrict__ se_b2,
                      const float* __restrict__ mlp_w1, const float* __restrict__ mlp_b1,
                      const float* __restrict__ mlp_w2, const float* __restrict__ mlp_b2) {
    int b = blockIdx.x, t = threadIdx.x;
    __shared__ float avg[CDIM], mx[CDIM], hse[12], ha[24], hm[24];

    avg[t] = g_sum[b*CDIM + t] * (1.0f/(float)HW);
    mx[t]  = u2f_ord(g_maxu[b*CDIM + t]);
    __syncthreads();

    if (t < 12) {
        float a = se_b1[t];
        for (int c = 0; c < CDIM; c++) a += avg[c] * se_w1[c*12 + t];
        hse[t] = swishf(a);
    } else if (t >= 32 && t < 56) {
        int j = t - 32;
        float a = mlp_b1[j], m = mlp_b1[j];
        for (int c = 0; c < CDIM; c++) {
            float w = mlp_w1[c*24 + j];
            a += avg[c]*w; m += mx[c]*w;
        }
        ha[j] = swishf(a); hm[j] = swishf(m);
    }
    __syncthreads();

    float s = se_b2[t];
    #pragma unroll
    for (int j = 0; j < 12; j++) s += hse[j] * se_w2[j*CDIM + t];
    float catt = 2.0f * mlp_b2[t];
    #pragma unroll
    for (int j = 0; j < 24; j++) catt += (ha[j] + hm[j]) * mlp_w2[j*CDIM + t];

    g_scale[b*CDIM + t] = sigm(s) * sigm(catt);
}

// ---------------- kernel 3: 7x7x2 conv + sigmoid (properly parallel) ------
// grid (8, B), block 256. Each block: 14 output rows. Tile = 20x118 float2
// of g_sp (L2-hot, ~19 KB smem). Each thread computes ~6 output pixels.
#define CROWS 14
__global__ void k_conv(const float* __restrict__ conv_k, const float* __restrict__ conv_b) {
    int b = blockIdx.y;
    int r0 = blockIdx.x * CROWS;
    int tid = threadIdx.x;

    __shared__ float2 tile[CROWS+6][WDIM+6];   // global rows r0-3..r0+16, cols -3..114
    __shared__ float2 kk2[49];
    __shared__ float  kb;

    for (int i = tid; i < (CROWS+6)*(WDIM+6); i += 256) {
        int tr = i / (WDIM+6);
        int tc = i - tr*(WDIM+6);
        int gh = r0 + tr - 3, gw = tc - 3;
        float2 v = make_float2(0.0f, 0.0f);
        if (gh >= 0 && gh < HDIM && gw >= 0 && gw < WDIM)
            v = g_sp[b*HW + gh*WDIM + gw];
        tile[tr][tc] = v;
    }
    if (tid < 49) kk2[tid] = ((const float2*)conv_k)[tid];
    if (tid == 0) kb = conv_b[0];
    __syncthreads();

    for (int p = tid; p < CROWS*WDIM; p += 256) {
        int r = p / WDIM, c = p - r*WDIM;
        float acc = kb;
        #pragma unroll
        for (int kh = 0; kh < 7; kh++)
            #pragma unroll
            for (int kw = 0; kw < 7; kw++) {
                float2 v = tile[r+kh][c+kw];
                float2 k = kk2[kh*7+kw];
                acc += v.x * k.x + v.y * k.y;
            }
        g_sa[b*HW + (r0+r)*WDIM + c] = sigm(acc);
    }
}

// ---------------- kernel 4: pure elementwise apply (float4 stream) --------
// grid (H, B), block (48, 8). sa row loaded once into smem; x/out streamed
// with evict-first hints (used once; keep L2 for the attention maps).
__global__ void k_apply(const float* __restrict__ x, float* __restrict__ out) {
    int b = blockIdx.y, h = blockIdx.x;
    int tid = threadIdx.y * C4 + threadIdx.x;

    __shared__ float sa[WDIM];
    if (tid < WDIM) sa[tid] = g_sa[b*HW + h*WDIM + tid];
    __syncthreads();

    int c4 = threadIdx.x, ty = threadIdx.y;
    float4 sc = ((const float4*)(g_scale + b*CDIM))[c4];
    const float4* xp = (const float4*)x + (size_t)(b*HW + h*WDIM) * C4;
    float4*       op = (float4*)out     + (size_t)(b*HW + h*WDIM) * C4;

    #pragma unroll 7
    for (int p = ty; p < WDIM; p += 8) {
        float s = sa[p];
        float4 v = __ldcs(xp + p*C4 + c4);
        v.x *= sc.x * s; v.y *= sc.y * s;
        v.z *= sc.z * s; v.w *= sc.w * s;
        __stcs(op + p*C4 + c4, v);
    }
}

// ---------------- launch ----------------
extern "C" void kernel_launch(void* const* d_in, const int* in_sizes, int n_in,
                              void* d_out, int out_size) {
    const float* x      = (const float*)d_in[0];
    const float* se_w1  = (const float*)d_in[1];
    const float* se_b1  = (const float*)d_in[2];
    const float* se_w2  = (const float*)d_in[3];
    const float* se_b2  = (const float*)d_in[4];
    const float* mlp_w1 = (const float*)d_in[5];
    const float* mlp_b1 = (const float*)d_in[6];
    const float* mlp_w2 = (const float*)d_in[7];
    const float* mlp_b2 = (const float*)d_in[8];
    const float* conv_k = (const float*)d_in[9];
    const float* conv_b = (const float*)d_in[10];
    float* out = (float*)d_out;

    k_init<<<(BATCH*CDIM + 255)/256, 256>>>();
    k_pool<<<dim3(HDIM/2, BATCH), 256>>>(x);
    k_mlp<<<BATCH, CDIM>>>(se_w1, se_b1, se_w2, se_b2, mlp_w1, mlp_b1, mlp_w2, mlp_b2);
    k_conv<<<dim3(HDIM/CROWS, BATCH), 256>>>(conv_k, conv_b);
    k_apply<<<dim3(HDIM, BATCH), dim3(C4, 8)>>>(x, out);
}